// round 6
// baseline (speedup 1.0000x reference)
#include <cuda_runtime.h>
#include <cstdint>

// HebbLinear: blk=1, bsz=256, ind=512, outd=512, float32.
//   y[b,o]      = bias[o] + sum_i x[b,i]*(w[i,o] + alpha[i]*hebb[b,i,o])
//   delta[b,i,o]= x[b,i] * y[b,o]
//
// R5 restructure: o-tile-owning CTAs. Mandatory DRAM traffic is ~537MB
// (hebb read 268 + delta write 268); R3/R4 showed DRAM stuck at ~75% with
// ~792MB of L2 traffic (w re-read 256MB by every sample-CTA) — plausibly
// LTS-cap bound. Here each CTA owns (o-tile of 16 outs x 16 samples), caches
// w[:,otile] (32KB) in smem ONCE, and streams hebb/delta slices per sample.
// w L2 traffic: 256MB -> 16MB. Grid 32x16=512 CTAs, 256 thr, 4 CTAs/SM.

#define IND    512
#define OUTD   512
#define BSZ    256
#define OUTD4  128        // OUTD/4
#define OTILE  16         // outputs per CTA
#define OT4    4          // OTILE/4 float4 columns
#define NOT    32         // OUTD/OTILE
#define BPG    16         // samples per CTA
#define NBG    16         // BSZ/BPG
#define THREADS 256
#define NIG    64         // THREADS/OT4 i-groups; i-step 64 -> 8 iters

__global__ __launch_bounds__(THREADS, 4)
void hebb_otile_kernel(const float* __restrict__ x,      // [BSZ, IND]
                       const float* __restrict__ hebb,   // [BSZ, IND, OUTD]
                       const float* __restrict__ w,      // [IND, OUTD]
                       const float* __restrict__ bias,   // [OUTD]
                       const float* __restrict__ alpha,  // [IND]
                       float* __restrict__ out,          // [BSZ, OUTD]
                       float* __restrict__ delta)        // [BSZ, IND, OUTD]
{
    __shared__ float4 sw[IND][OT4];   // 32 KB: w[:, otile]
    __shared__ float2 xx[IND];        // 4 KB: (x[b,i], x[b,i]*alpha[i])
    __shared__ float4 sred[8][OT4];   // per-warp partial sums
    __shared__ float4 sy[OT4];        // final y for this (b, otile)

    const int tid  = threadIdx.x;
    const int o4   = tid & (OT4 - 1);   // 0..3  float4 column within tile
    const int ig   = tid >> 2;          // 0..63 i-group
    const int wid  = tid >> 5;          // warp id 0..7
    const int lane = tid & 31;
    const int ob4  = blockIdx.x * OT4;  // global float4 column offset
    const int bbase = blockIdx.y * BPG;

    // ---- Cache w[:, otile] in smem (read from L2; shared by 16 CTAs/tile).
    const float4* w4 = (const float4*)w;
#pragma unroll
    for (int idx = tid; idx < IND * OT4; idx += THREADS) {
        sw[idx >> 2][idx & 3] = w4[(idx >> 2) * OUTD4 + ob4 + (idx & 3)];
    }
    float4 bv = make_float4(0.f, 0.f, 0.f, 0.f);
    if (tid < OT4) bv = ((const float4*)bias)[ob4 + tid];

    for (int bb = 0; bb < BPG; bb++) {
        const int b = bbase + bb;
        __syncthreads();                 // xx reuse guard (and sw ready, 1st iter)
        for (int idx = tid; idx < IND; idx += THREADS) {
            const float xv = x[b * IND + idx];
            xx[idx] = make_float2(xv, xv * alpha[idx]);
        }
        __syncthreads();

        // ---- Phase A: y partials. 8 fully-unrolled hebb LDG.128 per thread.
        const float4* hb =
            (const float4*)hebb + (size_t)b * (IND * OUTD4) + ob4 + o4;
        float4 acc = make_float4(0.f, 0.f, 0.f, 0.f);
#pragma unroll
        for (int i = ig; i < IND; i += NIG) {
            const float2 xv = xx[i];                       // broadcast LDS
            const float4 h  = __ldcs(hb + (size_t)i * OUTD4); // streaming read
            const float4 wv = sw[i][o4];                   // LDS (no L2!)
            acc.x = fmaf(xv.y, h.x, fmaf(xv.x, wv.x, acc.x));
            acc.y = fmaf(xv.y, h.y, fmaf(xv.x, wv.y, acc.y));
            acc.z = fmaf(xv.y, h.z, fmaf(xv.x, wv.z, acc.z));
            acc.w = fmaf(xv.y, h.w, fmaf(xv.x, wv.w, acc.w));
        }

        // ---- Reduce over ig: lanes 4/8/16 apart share the same o4.
#pragma unroll
        for (int d = 4; d < 32; d <<= 1) {
            acc.x += __shfl_xor_sync(0xffffffffu, acc.x, d);
            acc.y += __shfl_xor_sync(0xffffffffu, acc.y, d);
            acc.z += __shfl_xor_sync(0xffffffffu, acc.z, d);
            acc.w += __shfl_xor_sync(0xffffffffu, acc.w, d);
        }
        if (lane < OT4) sred[wid][lane] = acc;
        __syncthreads();

        if (tid < OT4) {
            float4 s = bv;
#pragma unroll
            for (int k = 0; k < 8; k++) {
                const float4 p = sred[k][tid];
                s.x += p.x; s.y += p.y; s.z += p.z; s.w += p.w;
            }
            sy[tid] = s;
            ((float4*)out)[b * OUTD4 + ob4 + tid] = s;   // publish y
        }
        __syncthreads();

        // ---- Phase B: delta[b,i,otile] = x[b,i] * y. Streaming stores.
        const float4 yv = sy[o4];
        float4* dd = (float4*)delta + (size_t)b * (IND * OUTD4) + ob4 + o4;
#pragma unroll
        for (int i = ig; i < IND; i += NIG) {
            const float xv = xx[i].x;
            __stcs(dd + (size_t)i * OUTD4,
                   make_float4(xv * yv.x, xv * yv.y, xv * yv.z, xv * yv.w));
        }
    }
}

extern "C" void kernel_launch(void* const* d_in, const int* in_sizes, int n_in,
                              void* d_out, int out_size)
{
    const float* x     = (const float*)d_in[0];  // (1, 256, 512)
    const float* hebb  = (const float*)d_in[1];  // (256, 512, 512)
    const float* w     = (const float*)d_in[2];  // (512, 512)
    const float* bias  = (const float*)d_in[3];  // (512,)
    const float* alpha = (const float*)d_in[4];  // (512,)

    float* out   = (float*)d_out;                // first BSZ*OUTD floats
    float* delta = out + (size_t)BSZ * OUTD;     // remaining BSZ*IND*OUTD

    dim3 grid(NOT, NBG);                         // 32 x 16 = 512 CTAs
    hebb_otile_kernel<<<grid, THREADS>>>(x, hebb, w, bias, alpha, out, delta);
}